// round 9
// baseline (speedup 1.0000x reference)
#include <cuda_runtime.h>
#include <cuda_fp16.h>
#include <math.h>

#define N_NODES 100000
#define N_EDGES 1600000
#define MAX_ITER 50

// ---------------- device scratch (static, no allocs) ----------------
__device__ __half g_F[(size_t)N_EDGES * 16];  // fp16 F sorted order, 16 halfs (32B)/edge
__device__ __half g_T[N_NODES * 16];          // fp16 per-node state@W1b
__device__ int    g_psrc[N_EDGES];
__device__ int    g_prow[N_EDGES];
__device__ float  g_pval[N_EDGES];
__device__ int    g_cnt[N_NODES];
__device__ int    g_cursor[N_NODES];
__device__ int    g_bsum[128];
__device__ int    g_bsumx[128];
__device__ float  g_state[N_NODES * 8];
__device__ float  g_new[N_NODES * 8];
__device__ int    g_flags[MAX_ITER + 1];
__device__ int    g_num;
__device__ unsigned g_barc;
__device__ unsigned g_barp;

// ---------------- constant weights ----------------
__constant__ float cW1a[8 * 15];
__constant__ float cW1b[5 * 15];
__constant__ float cb1[15];
__constant__ float cW2[15 * 5];
__constant__ float cb2[5];
__constant__ float cW3[5 * 10];
__constant__ float cb3[10];
__constant__ float cW4[10 * 7];
__constant__ float cb4[7];

__device__ __forceinline__ float tanh_fast(float x) {
    float y;
    asm("tanh.approx.f32 %0, %1;" : "=f"(y) : "f"(x));
    return y;
}
__device__ __forceinline__ __half2 tanh2_fast(__half2 h2) {
    unsigned hv; memcpy(&hv, &h2, 4);
    unsigned r;
    asm("tanh.approx.f16x2 %0, %1;" : "=r"(r) : "r"(hv));
    __half2 out; memcpy(&out, &r, 4);
    return out;
}

// compute T row (15 fp16 + pad) from 5 fp32 state values, store as 2x float4
__device__ __forceinline__ void store_T(int node, const float s[5]) {
    union { float4 v4[2]; __half2 h2[8]; } u;
    #pragma unroll
    for (int j = 0; j < 8; j++) {
        float lo = 0.f, hi = 0.f;
        #pragma unroll
        for (int d = 0; d < 5; d++) lo += s[d] * cW1b[d * 15 + 2 * j];
        if (2 * j + 1 < 15) {
            #pragma unroll
            for (int d = 0; d < 5; d++) hi += s[d] * cW1b[d * 15 + 2 * j + 1];
        }
        u.h2[j] = __floats2half2_rn(lo, hi);
    }
    float4* tp = (float4*)(g_T + (size_t)node * 16);
    tp[0] = u.v4[0];
    tp[1] = u.v4[1];
}

// monotonic-phase grid barrier; all blocks guaranteed resident by launch sizing
__device__ __forceinline__ void grid_barrier(unsigned nblocks, unsigned& phase) {
    __syncthreads();
    if (threadIdx.x == 0) {
        __threadfence();
        phase += 1;
        if (atomicAdd(&g_barc, 1u) == nblocks - 1u) {
            g_barc = 0u;
            __threadfence();
            atomicExch(&g_barp, phase);
        } else {
            while (atomicAdd(&g_barp, 0u) < phase) __nanosleep(64);
        }
        __threadfence();
    }
    __syncthreads();
}

// ---------------- init ----------------
__global__ void init_flags_kernel() {
    int t = threadIdx.x;
    if (t <= MAX_ITER) g_flags[t] = 0;
    if (t == 62) { g_barc = 0u; g_barp = 0u; }
    if (t == 63) g_num = 0;
}

__global__ __launch_bounds__(256) void init_nodes_kernel(
    const float* __restrict__ state_init,
    const float* __restrict__ old_init)
{
    int i = blockIdx.x * blockDim.x + threadIdx.x;
    bool exceed = false;
    if (i < N_NODES) {
        g_cnt[i] = 0;
        float s5[5];
        float d2 = 0.f;
        #pragma unroll
        for (int c = 0; c < 5; c++) {
            float s = state_init[i * 5 + c];
            float o = old_init[i * 5 + c];
            s5[c] = s;
            g_state[i * 8 + c] = s;
            g_new[i * 8 + c]   = 0.f;
            float d = s - o;
            d2 += d * d;
        }
        #pragma unroll
        for (int c = 5; c < 8; c++) {
            g_state[i * 8 + c] = 0.f;
            g_new[i * 8 + c]   = 0.f;
        }
        store_T(i, s5);
        exceed = sqrtf(d2 + 1e-11f) > 0.01f;
    }
    unsigned b = __ballot_sync(0xffffffffu, exceed);
    if ((threadIdx.x & 31) == 0 && b) atomicOr(&g_flags[0], 1);
}

// ---------------- counting sort by arc_rows ----------------
__global__ __launch_bounds__(256) void hist_kernel(const int* __restrict__ arc_rows) {
    int e = blockIdx.x * blockDim.x + threadIdx.x;
    if (e < N_EDGES) atomicAdd(&g_cnt[arc_rows[e]], 1);
}

__global__ __launch_bounds__(256) void scanA_kernel() {
    __shared__ int sh[256];
    int t = threadIdx.x, b = blockIdx.x;
    int base = b * 1024 + t * 4;
    int s = 0;
    #pragma unroll
    for (int j = 0; j < 4; j++) {
        int idx = base + j;
        if (idx < N_NODES) s += g_cnt[idx];
    }
    sh[t] = s; __syncthreads();
    for (int off = 1; off < 256; off <<= 1) {
        int v = (t >= off) ? sh[t - off] : 0;
        __syncthreads();
        sh[t] += v;
        __syncthreads();
    }
    if (t == 255) g_bsum[b] = sh[255];
}

__global__ void scanB_kernel(int nblocks) {
    if (threadIdx.x == 0) {
        int acc = 0;
        for (int b = 0; b < nblocks; b++) {
            g_bsumx[b] = acc;
            acc += g_bsum[b];
        }
    }
}

__global__ __launch_bounds__(256) void scanC_kernel() {
    __shared__ int sh[256];
    int t = threadIdx.x, b = blockIdx.x;
    int base = b * 1024 + t * 4;
    int c[4], s = 0;
    #pragma unroll
    for (int j = 0; j < 4; j++) {
        int idx = base + j;
        c[j] = (idx < N_NODES) ? g_cnt[idx] : 0;
        s += c[j];
    }
    sh[t] = s; __syncthreads();
    for (int off = 1; off < 256; off <<= 1) {
        int v = (t >= off) ? sh[t - off] : 0;
        __syncthreads();
        sh[t] += v;
        __syncthreads();
    }
    int excl = g_bsumx[b] + sh[t] - s;
    #pragma unroll
    for (int j = 0; j < 4; j++) {
        int idx = base + j;
        if (idx < N_NODES) g_cursor[idx] = excl;
        excl += c[j];
    }
}

// scatter edges into sorted order + compute F (fp16, linear per-edge)
__global__ __launch_bounds__(256) void scatter_precompute_kernel(
    const float* __restrict__ edge_feat,
    const int*   __restrict__ edge_src,
    const int*   __restrict__ arc_rows,
    const float* __restrict__ arc_vals)
{
    int e = blockIdx.x * blockDim.x + threadIdx.x;
    if (e >= N_EDGES) return;
    int row = arc_rows[e];
    int pos = atomicAdd(&g_cursor[row], 1);
    g_psrc[pos] = edge_src[e];
    g_prow[pos] = row;
    g_pval[pos] = arc_vals[e];

    const float4* efp = (const float4*)(edge_feat + (size_t)e * 8);
    float4 a0 = efp[0], a1 = efp[1];
    float ef[8] = {a0.x, a0.y, a0.z, a0.w, a1.x, a1.y, a1.z, a1.w};
    float v[16];
    #pragma unroll
    for (int j = 0; j < 15; j++) {
        float acc = cb1[j];
        #pragma unroll
        for (int d = 0; d < 8; d++) acc += ef[d] * cW1a[d * 15 + j];
        v[j] = acc;
    }
    v[15] = 0.f;
    union { float4 v4[2]; __half2 h2[8]; } u;
    #pragma unroll
    for (int j = 0; j < 8; j++)
        u.h2[j] = __floats2half2_rn(v[2 * j], v[2 * j + 1]);
    float4* op = (float4*)(g_F + (size_t)pos * 16);
    op[0] = u.v4[0];
    op[1] = u.v4[1];
}

// ---------------- persistent solver: all 50 iterations, grid barriers ----------------
__global__ __launch_bounds__(256) void solve_kernel(unsigned nblocks) {
    unsigned phase = 0;
    const int gsz  = (int)nblocks * 256;
    const int gtid = blockIdx.x * 256 + threadIdx.x;
    const int NPAIR = N_EDGES / 2;
    const unsigned FULL = 0xffffffffu;
    const int lane = threadIdx.x & 31;

    for (int k = 0; k < MAX_ITER; k++) {
        bool iter_active = (g_flags[k] != 0);

        if (iter_active) {
            // ---- edge phase: two sorted edges per thread ----
            for (int t = gtid; t < NPAIR; t += gsz) {
                int2   src2 = ((const int2*)g_psrc)[t];
                int2   row2 = ((const int2*)g_prow)[t];
                float2 av2  = ((const float2*)g_pval)[t];

                const float4* fp = (const float4*)(g_F + (size_t)t * 32);
                union UH { float4 v4[2]; __half2 h2[8]; };
                UH ufA, ufB, utA, utB;
                ufA.v4[0] = fp[0]; ufA.v4[1] = fp[1];
                ufB.v4[0] = fp[2]; ufB.v4[1] = fp[3];
                const float4* ta = (const float4*)(g_T + (size_t)src2.x * 16);
                const float4* tb = (const float4*)(g_T + (size_t)src2.y * 16);
                utA.v4[0] = ta[0]; utA.v4[1] = ta[1];
                utB.v4[0] = tb[0]; utB.v4[1] = tb[1];

                __half2 hA[8], hB[8];
                #pragma unroll
                for (int j = 0; j < 8; j++) {
                    hA[j] = tanh2_fast(__hadd2(ufA.h2[j], utA.h2[j]));
                    hB[j] = tanh2_fast(__hadd2(ufB.h2[j], utB.h2[j]));
                }

                float accA[5], accB[5];
                #pragma unroll
                for (int c = 0; c < 5; c++) { accA[c] = cb2[c]; accB[c] = cb2[c]; }
                #pragma unroll
                for (int j = 0; j < 15; j++) {
                    float a = (j & 1) ? __high2float(hA[j >> 1]) : __low2float(hA[j >> 1]);
                    float b = (j & 1) ? __high2float(hB[j >> 1]) : __low2float(hB[j >> 1]);
                    #pragma unroll
                    for (int c = 0; c < 5; c++) {
                        float w = cW2[j * 5 + c];
                        accA[c] += a * w;
                        accB[c] += b * w;
                    }
                }

                float v0[5], v1[5];
                #pragma unroll
                for (int c = 0; c < 5; c++) {
                    v0[c] = tanh_fast(accA[c]) * av2.x;
                    v1[c] = tanh_fast(accB[c]) * av2.y;
                }

                int  key = row2.y;
                bool split = (row2.x != row2.y);
                float val[5];
                #pragma unroll
                for (int c = 0; c < 5; c++) val[c] = split ? v1[c] : (v0[c] + v1[c]);
                if (split) {
                    #pragma unroll
                    for (int c = 0; c < 5; c++)
                        atomicAdd(&g_new[row2.x * 8 + c], v0[c]);
                }

                int pkey = __shfl_up_sync(FULL, key, 1);
                bool head = (lane == 0) || (pkey != key);
                #pragma unroll
                for (int off = 1; off < 32; off <<= 1) {
                    int k2 = __shfl_down_sync(FULL, key, off);
                    bool ok = (lane + off < 32) && (k2 == key);
                    #pragma unroll
                    for (int c = 0; c < 5; c++) {
                        float s = __shfl_down_sync(FULL, val[c], off);
                        if (ok) val[c] += s;
                    }
                }
                if (head) {
                    #pragma unroll
                    for (int c = 0; c < 5; c++)
                        atomicAdd(&g_new[key * 8 + c], val[c]);
                }
            }
        }

        grid_barrier(nblocks, phase);

        if (iter_active) {
            // ---- update phase ----
            for (int i = gtid; i < N_NODES; i += gsz) {
                float4* np = (float4*)(g_new + i * 8);
                float4* sp = (float4*)(g_state + i * 8);
                float4 n0 = np[0], n1 = np[1];
                float4 s0 = sp[0], s1 = sp[1];
                sp[0] = n0; sp[1] = n1;
                np[0] = make_float4(0.f, 0.f, 0.f, 0.f);
                np[1] = make_float4(0.f, 0.f, 0.f, 0.f);
                float s5[5] = {n0.x, n0.y, n0.z, n0.w, n1.x};
                store_T(i, s5);
                float dx = n0.x - s0.x, dy = n0.y - s0.y, dz = n0.z - s0.z,
                      dw = n0.w - s0.w, d4 = n1.x - s1.x;
                float d2 = dx * dx + dy * dy + dz * dz + dw * dw + d4 * d4;
                bool exceed = sqrtf(d2 + 1e-11f) > 0.01f;
                unsigned b = __ballot_sync(__activemask(), exceed);
                if ((lane == 0 || i == gtid) && b)   // leader of active subset
                    atomicOr(&g_flags[k + 1], 1);
            }
            if (gtid == 0) g_num += 1;
        }

        grid_barrier(nblocks, phase);
    }
}

// ---------------- output ----------------
__global__ __launch_bounds__(256) void output_kernel(float* __restrict__ out, int out_size) {
    int i = blockIdx.x * blockDim.x + threadIdx.x;
    if (i >= N_NODES) return;

    float s[5];
    #pragma unroll
    for (int c = 0; c < 5; c++) s[c] = g_state[i * 8 + c];

    float o1[10];
    #pragma unroll
    for (int j = 0; j < 10; j++) {
        float a = cb3[j];
        #pragma unroll
        for (int c = 0; c < 5; c++) a += s[c] * cW3[c * 10 + j];
        o1[j] = tanh_fast(a);
    }

    float l[7];
    #pragma unroll
    for (int c = 0; c < 7; c++) {
        float a = cb4[c];
        #pragma unroll
        for (int j = 0; j < 10; j++) a += o1[j] * cW4[j * 7 + c];
        l[c] = a;
    }

    float m = l[0];
    #pragma unroll
    for (int c = 1; c < 7; c++) m = fmaxf(m, l[c]);
    float ex[7];
    float sum = 0.f;
    #pragma unroll
    for (int c = 0; c < 7; c++) { ex[c] = __expf(l[c] - m); sum += ex[c]; }
    float inv = 1.0f / sum;
    #pragma unroll
    for (int c = 0; c < 7; c++) out[i * 7 + c] = ex[c] * inv;

    if (i == 0 && out_size > N_NODES * 7) {
        out[N_NODES * 7] = (float)g_num;
    }
}

// ---------------- launcher ----------------
extern "C" void kernel_launch(void* const* d_in, const int* in_sizes, int n_in,
                              void* d_out, int out_size)
{
    const float* edge_feat  = (const float*)d_in[0];
    const int*   edge_src   = (const int*)  d_in[1];
    const int*   arc_rows   = (const int*)  d_in[2];
    const float* arc_vals   = (const float*)d_in[3];
    const float* state_init = (const float*)d_in[4];
    const float* old_init   = (const float*)d_in[5];
    const float* W1 = (const float*)d_in[6];
    const float* b1 = (const float*)d_in[7];
    const float* W2 = (const float*)d_in[8];
    const float* b2 = (const float*)d_in[9];
    const float* W3 = (const float*)d_in[10];
    const float* b3 = (const float*)d_in[11];
    const float* W4 = (const float*)d_in[12];
    const float* b4 = (const float*)d_in[13];

    cudaMemcpyToSymbolAsync(cW1a, W1,           8 * 15 * sizeof(float), 0, cudaMemcpyDeviceToDevice, 0);
    cudaMemcpyToSymbolAsync(cW1b, W1 + 8 * 15,  5 * 15 * sizeof(float), 0, cudaMemcpyDeviceToDevice, 0);
    cudaMemcpyToSymbolAsync(cb1,  b1,           15 * sizeof(float),     0, cudaMemcpyDeviceToDevice, 0);
    cudaMemcpyToSymbolAsync(cW2,  W2,           15 * 5 * sizeof(float), 0, cudaMemcpyDeviceToDevice, 0);
    cudaMemcpyToSymbolAsync(cb2,  b2,           5 * sizeof(float),      0, cudaMemcpyDeviceToDevice, 0);
    cudaMemcpyToSymbolAsync(cW3,  W3,           5 * 10 * sizeof(float), 0, cudaMemcpyDeviceToDevice, 0);
    cudaMemcpyToSymbolAsync(cb3,  b3,           10 * sizeof(float),     0, cudaMemcpyDeviceToDevice, 0);
    cudaMemcpyToSymbolAsync(cW4,  W4,           10 * 7 * sizeof(float), 0, cudaMemcpyDeviceToDevice, 0);
    cudaMemcpyToSymbolAsync(cb4,  b4,           7 * sizeof(float),      0, cudaMemcpyDeviceToDevice, 0);

    const int NODE_BLOCKS = (N_NODES + 255) / 256;
    const int EDGE_BLOCKS = (N_EDGES + 255) / 256;   // 6250
    const int SCAN_BLOCKS = (N_NODES + 1023) / 1024; // 98

    // size persistent grid so ALL blocks are co-resident (no barrier deadlock)
    int dev = 0;
    cudaGetDevice(&dev);
    int nsm = 0;
    cudaDeviceGetAttribute(&nsm, cudaDevAttrMultiProcessorCount, dev);
    int maxb = 0;
    cudaOccupancyMaxActiveBlocksPerMultiprocessor(&maxb, solve_kernel, 256, 0);
    if (maxb < 1) maxb = 1;
    long long cap = (long long)maxb * (long long)nsm;
    long long want = (N_EDGES / 2 + 255) / 256;      // 3125
    unsigned grid = (unsigned)((cap < want) ? cap : want);
    if (grid < 1) grid = 1;

    init_flags_kernel<<<1, 64>>>();
    init_nodes_kernel<<<NODE_BLOCKS, 256>>>(state_init, old_init);

    hist_kernel<<<EDGE_BLOCKS, 256>>>(arc_rows);
    scanA_kernel<<<SCAN_BLOCKS, 256>>>();
    scanB_kernel<<<1, 32>>>(SCAN_BLOCKS);
    scanC_kernel<<<SCAN_BLOCKS, 256>>>();
    scatter_precompute_kernel<<<EDGE_BLOCKS, 256>>>(edge_feat, edge_src, arc_rows, arc_vals);

    solve_kernel<<<grid, 256>>>(grid);

    output_kernel<<<NODE_BLOCKS, 256>>>((float*)d_out, out_size);
}

// round 10
// speedup vs baseline: 1.2350x; 1.2350x over previous
#include <cuda_runtime.h>
#include <cuda_fp16.h>
#include <math.h>

#define N_NODES 100000
#define N_EDGES 1600000
#define MAX_ITER 50

typedef unsigned long long u64;

// ---------------- device scratch (static, no allocs) ----------------
__device__ __half g_F[(size_t)N_EDGES * 16];  // fp16 F sorted order, 16 halfs (32B)/edge
__device__ u64    g_meta[N_EDGES];            // src(17b) | row(17b)<<17 | valq(30b)<<34
__device__ __half g_s16[N_NODES * 8];         // fp16 state mirror, 16B/node (1 wavefront gather)
__device__ int    g_cnt[N_NODES];
__device__ int    g_cursor[N_NODES];
__device__ int    g_bsum[128];
__device__ int    g_bsumx[128];
__device__ float  g_state[N_NODES * 8];
__device__ float  g_new[N_NODES * 8];
__device__ int    g_flags[MAX_ITER + 1];
__device__ int    g_num;

// ---------------- constant weights ----------------
__constant__ float cW1a[8 * 15];
__constant__ float cW1b[5 * 15];
__constant__ float cb1[15];
__constant__ float cW2[15 * 5];
__constant__ float cb2[5];
__constant__ float cW3[5 * 10];
__constant__ float cb3[10];
__constant__ float cW4[10 * 7];
__constant__ float cb4[7];

__device__ __forceinline__ float tanh_fast(float x) {
    float y;
    asm("tanh.approx.f32 %0, %1;" : "=f"(y) : "f"(x));
    return y;
}

// store fp16 state mirror (5 halfs + pad to 16B)
__device__ __forceinline__ void store_s16(int node, const float s[5]) {
    union { float4 v4; __half2 h2[4]; } u;
    u.h2[0] = __floats2half2_rn(s[0], s[1]);
    u.h2[1] = __floats2half2_rn(s[2], s[3]);
    u.h2[2] = __floats2half2_rn(s[4], 0.f);
    u.h2[3] = __floats2half2_rn(0.f, 0.f);
    *(float4*)(g_s16 + (size_t)node * 8) = u.v4;
}

// ---------------- init ----------------
__global__ void init_flags_kernel() {
    int t = threadIdx.x;
    if (t <= MAX_ITER) g_flags[t] = 0;
    if (t == 63) g_num = 0;
}

__global__ __launch_bounds__(256) void init_nodes_kernel(
    const float* __restrict__ state_init,
    const float* __restrict__ old_init)
{
    int i = blockIdx.x * blockDim.x + threadIdx.x;
    bool exceed = false;
    if (i < N_NODES) {
        g_cnt[i] = 0;
        float s5[5];
        float d2 = 0.f;
        #pragma unroll
        for (int c = 0; c < 5; c++) {
            float s = state_init[i * 5 + c];
            float o = old_init[i * 5 + c];
            s5[c] = s;
            g_state[i * 8 + c] = s;
            g_new[i * 8 + c]   = 0.f;
            float d = s - o;
            d2 += d * d;
        }
        #pragma unroll
        for (int c = 5; c < 8; c++) {
            g_state[i * 8 + c] = 0.f;
            g_new[i * 8 + c]   = 0.f;
        }
        store_s16(i, s5);
        exceed = sqrtf(d2 + 1e-11f) > 0.01f;
    }
    unsigned b = __ballot_sync(0xffffffffu, exceed);
    if ((threadIdx.x & 31) == 0 && b) atomicOr(&g_flags[0], 1);
}

// ---------------- counting sort by arc_rows ----------------
__global__ __launch_bounds__(256) void hist_kernel(const int* __restrict__ arc_rows) {
    int e = blockIdx.x * blockDim.x + threadIdx.x;
    if (e < N_EDGES) atomicAdd(&g_cnt[arc_rows[e]], 1);
}

__global__ __launch_bounds__(256) void scanA_kernel() {
    __shared__ int sh[256];
    int t = threadIdx.x, b = blockIdx.x;
    int base = b * 1024 + t * 4;
    int s = 0;
    #pragma unroll
    for (int j = 0; j < 4; j++) {
        int idx = base + j;
        if (idx < N_NODES) s += g_cnt[idx];
    }
    sh[t] = s; __syncthreads();
    for (int off = 1; off < 256; off <<= 1) {
        int v = (t >= off) ? sh[t - off] : 0;
        __syncthreads();
        sh[t] += v;
        __syncthreads();
    }
    if (t == 255) g_bsum[b] = sh[255];
}

__global__ void scanB_kernel(int nblocks) {
    if (threadIdx.x == 0) {
        int acc = 0;
        for (int b = 0; b < nblocks; b++) {
            g_bsumx[b] = acc;
            acc += g_bsum[b];
        }
    }
}

__global__ __launch_bounds__(256) void scanC_kernel() {
    __shared__ int sh[256];
    int t = threadIdx.x, b = blockIdx.x;
    int base = b * 1024 + t * 4;
    int c[4], s = 0;
    #pragma unroll
    for (int j = 0; j < 4; j++) {
        int idx = base + j;
        c[j] = (idx < N_NODES) ? g_cnt[idx] : 0;
        s += c[j];
    }
    sh[t] = s; __syncthreads();
    for (int off = 1; off < 256; off <<= 1) {
        int v = (t >= off) ? sh[t - off] : 0;
        __syncthreads();
        sh[t] += v;
        __syncthreads();
    }
    int excl = g_bsumx[b] + sh[t] - s;
    #pragma unroll
    for (int j = 0; j < 4; j++) {
        int idx = base + j;
        if (idx < N_NODES) g_cursor[idx] = excl;
        excl += c[j];
    }
}

// scatter edges into sorted order + compute F (fp16) + packed meta
__global__ __launch_bounds__(256) void scatter_precompute_kernel(
    const float* __restrict__ edge_feat,
    const int*   __restrict__ edge_src,
    const int*   __restrict__ arc_rows,
    const float* __restrict__ arc_vals)
{
    int e = blockIdx.x * blockDim.x + threadIdx.x;
    if (e >= N_EDGES) return;
    int row = arc_rows[e];
    int pos = atomicAdd(&g_cursor[row], 1);

    float av = arc_vals[e];
    u64 valq = (u64)(av * 1073741824.0f);          // 2^30, av in [0,1)
    if (valq > 0x3FFFFFFFull) valq = 0x3FFFFFFFull;
    g_meta[pos] = (u64)(unsigned)edge_src[e] | ((u64)(unsigned)row << 17) | (valq << 34);

    const float4* efp = (const float4*)(edge_feat + (size_t)e * 8);
    float4 a0 = efp[0], a1 = efp[1];
    float ef[8] = {a0.x, a0.y, a0.z, a0.w, a1.x, a1.y, a1.z, a1.w};
    float v[16];
    #pragma unroll
    for (int j = 0; j < 15; j++) {
        float acc = cb1[j];
        #pragma unroll
        for (int d = 0; d < 8; d++) acc += ef[d] * cW1a[d * 15 + j];
        v[j] = acc;
    }
    v[15] = 0.f;
    union { float4 v4[2]; __half2 h2[8]; } u;
    #pragma unroll
    for (int j = 0; j < 8; j++)
        u.h2[j] = __floats2half2_rn(v[2 * j], v[2 * j + 1]);
    float4* op = (float4*)(g_F + (size_t)pos * 16);
    op[0] = u.v4[0];
    op[1] = u.v4[1];
}

// ---------------- per-iteration kernels ----------------
__global__ __launch_bounds__(256) void edge_kernel(int k)
{
    if (g_flags[k] == 0) return;
    int e = blockIdx.x * blockDim.x + threadIdx.x;   // grid exactly covers N_EDGES

    u64 m = g_meta[e];
    int   src = (int)(m & 0x1FFFFull);
    int   row = (int)((m >> 17) & 0x1FFFFull);
    float av  = (float)(unsigned)(m >> 34) * (1.0f / 1073741824.0f);

    // ONE 16B scattered gather: fp16 state
    float4 sv = *(const float4*)(g_s16 + (size_t)src * 8);
    __half2* sh = (__half2*)&sv;
    float2 s01 = __half22float2(sh[0]);
    float2 s23 = __half22float2(sh[1]);
    float2 s4x = __half22float2(sh[2]);
    float s0 = s01.x, s1 = s01.y, s2 = s23.x, s3 = s23.y, s4 = s4x.x;

    // coalesced F (32B)
    const float4* fp = (const float4*)(g_F + (size_t)e * 16);
    union { float4 v4[2]; __half2 h2[8]; } uf;
    uf.v4[0] = fp[0]; uf.v4[1] = fp[1];
    float fr[16];
    #pragma unroll
    for (int j = 0; j < 8; j++) {
        float2 t = __half22float2(uf.h2[j]);
        fr[2 * j]     = t.x;
        fr[2 * j + 1] = t.y;
    }

    float h1[15];
    #pragma unroll
    for (int j = 0; j < 15; j++) {
        float a = fr[j];
        a += s0 * cW1b[0 * 15 + j];
        a += s1 * cW1b[1 * 15 + j];
        a += s2 * cW1b[2 * 15 + j];
        a += s3 * cW1b[3 * 15 + j];
        a += s4 * cW1b[4 * 15 + j];
        h1[j] = tanh_fast(a);
    }

    float v[5];
    #pragma unroll
    for (int c = 0; c < 5; c++) {
        float a = cb2[c];
        #pragma unroll
        for (int j = 0; j < 15; j++) a += h1[j] * cW2[j * 5 + c];
        v[c] = tanh_fast(a) * av;
    }

    // warp-segmented suffix reduction over contiguous equal-row runs
    const unsigned FULL = 0xffffffffu;
    int lane = threadIdx.x & 31;
    int prow = __shfl_up_sync(FULL, row, 1);
    bool head = (lane == 0) || (prow != row);

    #pragma unroll
    for (int off = 1; off < 32; off <<= 1) {
        int r2 = __shfl_down_sync(FULL, row, off);
        bool ok = (lane + off < 32) && (r2 == row);
        #pragma unroll
        for (int c = 0; c < 5; c++) {
            float t = __shfl_down_sync(FULL, v[c], off);
            if (ok) v[c] += t;
        }
    }

    if (head) {
        #pragma unroll
        for (int c = 0; c < 5; c++)
            atomicAdd(&g_new[row * 8 + c], v[c]);
    }
}

__global__ __launch_bounds__(256) void update_kernel(int k) {
    if (g_flags[k] == 0) return;
    int i = blockIdx.x * blockDim.x + threadIdx.x;
    bool exceed = false;
    if (i < N_NODES) {
        float4* np = (float4*)(g_new + i * 8);
        float4* sp = (float4*)(g_state + i * 8);
        float4 n0 = np[0], n1 = np[1];
        float4 s0 = sp[0], s1 = sp[1];
        sp[0] = n0; sp[1] = n1;
        np[0] = make_float4(0.f, 0.f, 0.f, 0.f);
        np[1] = make_float4(0.f, 0.f, 0.f, 0.f);
        float s5[5] = {n0.x, n0.y, n0.z, n0.w, n1.x};
        store_s16(i, s5);
        float dx = n0.x - s0.x, dy = n0.y - s0.y, dz = n0.z - s0.z,
              dw = n0.w - s0.w, d4 = n1.x - s1.x;
        float d2 = dx * dx + dy * dy + dz * dz + dw * dw + d4 * d4;
        exceed = sqrtf(d2 + 1e-11f) > 0.01f;
        if (i == 0) g_num += 1;
    }
    unsigned b = __ballot_sync(0xffffffffu, exceed);
    if ((threadIdx.x & 31) == 0 && b) atomicOr(&g_flags[k + 1], 1);
}

__global__ __launch_bounds__(256) void output_kernel(float* __restrict__ out, int out_size) {
    int i = blockIdx.x * blockDim.x + threadIdx.x;
    if (i >= N_NODES) return;

    float s[5];
    #pragma unroll
    for (int c = 0; c < 5; c++) s[c] = g_state[i * 8 + c];

    float o1[10];
    #pragma unroll
    for (int j = 0; j < 10; j++) {
        float a = cb3[j];
        #pragma unroll
        for (int c = 0; c < 5; c++) a += s[c] * cW3[c * 10 + j];
        o1[j] = tanh_fast(a);
    }

    float l[7];
    #pragma unroll
    for (int c = 0; c < 7; c++) {
        float a = cb4[c];
        #pragma unroll
        for (int j = 0; j < 10; j++) a += o1[j] * cW4[j * 7 + c];
        l[c] = a;
    }

    float m = l[0];
    #pragma unroll
    for (int c = 1; c < 7; c++) m = fmaxf(m, l[c]);
    float ex[7];
    float sum = 0.f;
    #pragma unroll
    for (int c = 0; c < 7; c++) { ex[c] = __expf(l[c] - m); sum += ex[c]; }
    float inv = 1.0f / sum;
    #pragma unroll
    for (int c = 0; c < 7; c++) out[i * 7 + c] = ex[c] * inv;

    if (i == 0 && out_size > N_NODES * 7) {
        out[N_NODES * 7] = (float)g_num;
    }
}

// ---------------- launcher ----------------
extern "C" void kernel_launch(void* const* d_in, const int* in_sizes, int n_in,
                              void* d_out, int out_size)
{
    const float* edge_feat  = (const float*)d_in[0];
    const int*   edge_src   = (const int*)  d_in[1];
    const int*   arc_rows   = (const int*)  d_in[2];
    const float* arc_vals   = (const float*)d_in[3];
    const float* state_init = (const float*)d_in[4];
    const float* old_init   = (const float*)d_in[5];
    const float* W1 = (const float*)d_in[6];
    const float* b1 = (const float*)d_in[7];
    const float* W2 = (const float*)d_in[8];
    const float* b2 = (const float*)d_in[9];
    const float* W3 = (const float*)d_in[10];
    const float* b3 = (const float*)d_in[11];
    const float* W4 = (const float*)d_in[12];
    const float* b4 = (const float*)d_in[13];

    cudaMemcpyToSymbolAsync(cW1a, W1,           8 * 15 * sizeof(float), 0, cudaMemcpyDeviceToDevice, 0);
    cudaMemcpyToSymbolAsync(cW1b, W1 + 8 * 15,  5 * 15 * sizeof(float), 0, cudaMemcpyDeviceToDevice, 0);
    cudaMemcpyToSymbolAsync(cb1,  b1,           15 * sizeof(float),     0, cudaMemcpyDeviceToDevice, 0);
    cudaMemcpyToSymbolAsync(cW2,  W2,           15 * 5 * sizeof(float), 0, cudaMemcpyDeviceToDevice, 0);
    cudaMemcpyToSymbolAsync(cb2,  b2,           5 * sizeof(float),      0, cudaMemcpyDeviceToDevice, 0);
    cudaMemcpyToSymbolAsync(cW3,  W3,           5 * 10 * sizeof(float), 0, cudaMemcpyDeviceToDevice, 0);
    cudaMemcpyToSymbolAsync(cb3,  b3,           10 * sizeof(float),     0, cudaMemcpyDeviceToDevice, 0);
    cudaMemcpyToSymbolAsync(cW4,  W4,           10 * 7 * sizeof(float), 0, cudaMemcpyDeviceToDevice, 0);
    cudaMemcpyToSymbolAsync(cb4,  b4,           7 * sizeof(float),      0, cudaMemcpyDeviceToDevice, 0);

    const int NODE_BLOCKS = (N_NODES + 255) / 256;
    const int EDGE_BLOCKS = (N_EDGES + 255) / 256;   // 6250
    const int SCAN_BLOCKS = (N_NODES + 1023) / 1024; // 98

    init_flags_kernel<<<1, 64>>>();
    init_nodes_kernel<<<NODE_BLOCKS, 256>>>(state_init, old_init);

    hist_kernel<<<EDGE_BLOCKS, 256>>>(arc_rows);
    scanA_kernel<<<SCAN_BLOCKS, 256>>>();
    scanB_kernel<<<1, 32>>>(SCAN_BLOCKS);
    scanC_kernel<<<SCAN_BLOCKS, 256>>>();
    scatter_precompute_kernel<<<EDGE_BLOCKS, 256>>>(edge_feat, edge_src, arc_rows, arc_vals);

    for (int k = 0; k < MAX_ITER; k++) {
        edge_kernel<<<EDGE_BLOCKS, 256>>>(k);
        update_kernel<<<NODE_BLOCKS, 256>>>(k);
    }

    output_kernel<<<NODE_BLOCKS, 256>>>((float*)d_out, out_size);
}